// round 2
// baseline (speedup 1.0000x reference)
#include <cuda_runtime.h>
#include <math.h>

#define DIM      16
#define HID      128
#define NB       1024
#define NSTEPS   10
#define ROWS     17
#define NTHREADS 128

// Intermediate storage (no allocations allowed)
__device__ float g_Y[2 * NB * DIM];        // y_comb: [2048][16]
__device__ float g_J[NB * DIM * DIM];      // J[b][i][j] = d flow(x)_i / d x_j

struct Weights {
    const float* W0; const float* b0;
    const float* W1; const float* b1;
    const float* W2; const float* b2;
    const float* W3; const float* b3;
    const float* W4; const float* b4;
};

struct Smem {
    float Z[ROWS][DIM];     // integration state (row 0 primal, rows 1..16 tangents / extra primals)
    float Zin[ROWS][DIM];   // vel input
    float Ks[ROWS][DIM];    // RK4 accumulator
    float V[ROWS][DIM];     // vel output
    float H[2][ROWS][HID];  // hidden ping-pong
};

// One velocity-field evaluation for all ROWS state rows.
// JAC=true : row 0 is primal (bias + t col + tanh), rows 1..16 are tangents
//            (no bias/t, scaled by (1 - h^2) of the primal).
// JAC=false: every row is an independent primal sample.
template <bool JAC>
__device__ __forceinline__ void vel_eval(Smem& sm, float t, const Weights& w)
{
    const int j = threadIdx.x;
    float acc[ROWS];

    // ---- layer 0: in 16 (+t for primal) -> 128 ----
    {
        float bt = t * __ldg(w.W0 + DIM * HID + j) + __ldg(w.b0 + j);
        #pragma unroll
        for (int s = 0; s < ROWS; s++) acc[s] = (JAC && s > 0) ? 0.f : bt;
        #pragma unroll
        for (int i = 0; i < DIM; i++) {
            float ww = __ldg(w.W0 + i * HID + j);
            #pragma unroll
            for (int s = 0; s < ROWS; s++) acc[s] = fmaf(sm.Zin[s][i], ww, acc[s]);
        }
        if (JAC) {
            float h = tanhf(acc[0]);
            float g = 1.f - h * h;
            sm.H[0][0][j] = h;
            #pragma unroll
            for (int s = 1; s < ROWS; s++) sm.H[0][s][j] = g * acc[s];
        } else {
            #pragma unroll
            for (int s = 0; s < ROWS; s++) sm.H[0][s][j] = tanhf(acc[s]);
        }
    }
    __syncthreads();

    // ---- layers 1..3: 128 -> 128 ----
    #pragma unroll
    for (int L = 0; L < 3; L++) {
        const float* W  = (L == 0) ? w.W1 : (L == 1) ? w.W2 : w.W3;
        const float* bb = (L == 0) ? w.b1 : (L == 1) ? w.b2 : w.b3;
        const float (*Hin)[HID] = sm.H[L & 1];
        float (*Hout)[HID]      = sm.H[(L + 1) & 1];

        float bj = __ldg(bb + j);
        #pragma unroll
        for (int s = 0; s < ROWS; s++) acc[s] = (JAC && s > 0) ? 0.f : bj;

        #pragma unroll 4
        for (int i = 0; i < HID; i++) {
            float ww = __ldg(W + i * HID + j);
            #pragma unroll
            for (int s = 0; s < ROWS; s++) acc[s] = fmaf(Hin[s][i], ww, acc[s]);
        }
        if (JAC) {
            float h = tanhf(acc[0]);
            float g = 1.f - h * h;
            Hout[0][j] = h;
            #pragma unroll
            for (int s = 1; s < ROWS; s++) Hout[s][j] = g * acc[s];
        } else {
            #pragma unroll
            for (int s = 0; s < ROWS; s++) Hout[s][j] = tanhf(acc[s]);
        }
        __syncthreads();
    }

    // ---- layer 4: 128 -> 16 (linear, no activation) ----
    if (j < DIM) {
        const float (*Hin)[HID] = sm.H[1];
        float bj = __ldg(w.b4 + j);
        #pragma unroll
        for (int s = 0; s < ROWS; s++) acc[s] = (JAC && s > 0) ? 0.f : bj;
        #pragma unroll 4
        for (int i = 0; i < HID; i++) {
            float ww = __ldg(w.W4 + i * DIM + j);
            #pragma unroll
            for (int s = 0; s < ROWS; s++) acc[s] = fmaf(Hin[s][i], ww, acc[s]);
        }
        #pragma unroll
        for (int s = 0; s < ROWS; s++) sm.V[s][j] = acc[s];
    }
    __syncthreads();
}

template <bool JAC>
__device__ __forceinline__ void rk4_step(Smem& sm, float t, float dt, const Weights& w)
{
    const int tid = threadIdx.x;

    vel_eval<JAC>(sm, t, w);                       // k1 (Zin == Z on entry)
    for (int e = tid; e < ROWS * DIM; e += NTHREADS) {
        int r = e / DIM, c = e % DIM;
        float v = sm.V[r][c];
        sm.Ks[r][c]  = v;
        sm.Zin[r][c] = sm.Z[r][c] + 0.5f * dt * v;
    }
    __syncthreads();

    vel_eval<JAC>(sm, t + 0.5f * dt, w);           // k2
    for (int e = tid; e < ROWS * DIM; e += NTHREADS) {
        int r = e / DIM, c = e % DIM;
        float v = sm.V[r][c];
        sm.Ks[r][c] += 2.f * v;
        sm.Zin[r][c] = sm.Z[r][c] + 0.5f * dt * v;
    }
    __syncthreads();

    vel_eval<JAC>(sm, t + 0.5f * dt, w);           // k3
    for (int e = tid; e < ROWS * DIM; e += NTHREADS) {
        int r = e / DIM, c = e % DIM;
        float v = sm.V[r][c];
        sm.Ks[r][c] += 2.f * v;
        sm.Zin[r][c] = sm.Z[r][c] + dt * v;
    }
    __syncthreads();

    vel_eval<JAC>(sm, t + dt, w);                  // k4
    for (int e = tid; e < ROWS * DIM; e += NTHREADS) {
        int r = e / DIM, c = e % DIM;
        float z = sm.Z[r][c] + (sm.Ks[r][c] + sm.V[r][c]) * (dt / 6.f);
        sm.Z[r][c]   = z;
        sm.Zin[r][c] = z;
    }
    __syncthreads();
}

__global__ __launch_bounds__(NTHREADS, 8) void flow_kernel(
    const float* __restrict__ x, const float* __restrict__ xs, Weights w)
{
    __shared__ Smem sm;
    const int tid = threadIdx.x;
    const bool jac = (blockIdx.x < NB);

    // ---- init state rows ----
    if (jac) {
        int b = blockIdx.x;
        for (int e = tid; e < ROWS * DIM; e += NTHREADS) {
            int r = e / DIM, c = e % DIM;
            float v = (r == 0) ? x[b * DIM + c] : ((r - 1) == c ? 1.f : 0.f);
            sm.Z[r][c] = v; sm.Zin[r][c] = v;
        }
    } else {
        int cta = blockIdx.x - NB;
        for (int e = tid; e < ROWS * DIM; e += NTHREADS) {
            int r = e / DIM, c = e % DIM;
            int idx = cta * ROWS + r;
            float v = (idx < NB) ? xs[idx * DIM + c] : 0.f;
            sm.Z[r][c] = v; sm.Zin[r][c] = v;
        }
    }
    __syncthreads();

    const float dt = 1.f / NSTEPS;
    for (int step = 0; step < NSTEPS; step++) {
        float t = step * dt;
        if (jac) rk4_step<true>(sm, t, dt, w);
        else     rk4_step<false>(sm, t, dt, w);
    }

    // ---- writeback ----
    if (jac) {
        int b = blockIdx.x;
        for (int e = tid; e < ROWS * DIM; e += NTHREADS) {
            int r = e / DIM, c = e % DIM;
            if (r == 0) g_Y[b * DIM + c] = sm.Z[0][c];
            else        g_J[b * DIM * DIM + c * DIM + (r - 1)] = sm.Z[r][c];
        }
    } else {
        int cta = blockIdx.x - NB;
        for (int e = tid; e < ROWS * DIM; e += NTHREADS) {
            int r = e / DIM, c = e % DIM;
            int idx = cta * ROWS + r;
            if (idx < NB) g_Y[(NB + idx) * DIM + c] = sm.Z[r][c];
        }
    }
}

// Per-sample: g = (y - y*)/(||y-y*||+1e-8); gx = J^T g; G = J^T J + 1e-6 I;
// out = -G^{-1} gx via Cholesky (G is SPD).
__global__ void solve_kernel(float* __restrict__ out)
{
    int b = blockIdx.x * blockDim.x + threadIdx.x;
    if (b >= NB) return;

    float Jm[DIM][DIM];
    for (int i = 0; i < DIM; i++)
        for (int j = 0; j < DIM; j++)
            Jm[i][j] = g_J[b * DIM * DIM + i * DIM + j];

    float diff[DIM]; float ss = 0.f;
    for (int i = 0; i < DIM; i++) {
        float d = g_Y[b * DIM + i] - g_Y[(NB + b) * DIM + i];
        diff[i] = d; ss += d * d;
    }
    float inorm = 1.f / (sqrtf(ss) + 1e-8f);

    float gx[DIM];
    for (int j = 0; j < DIM; j++) {
        float s = 0.f;
        for (int i = 0; i < DIM; i++) s += Jm[i][j] * diff[i];
        gx[j] = s * inorm;
    }

    float G[DIM][DIM];
    for (int j = 0; j < DIM; j++)
        for (int k = 0; k <= j; k++) {
            float s = 0.f;
            for (int i = 0; i < DIM; i++) s += Jm[i][j] * Jm[i][k];
            G[j][k] = s; G[k][j] = s;
        }
    for (int j = 0; j < DIM; j++) G[j][j] += 1e-6f;

    // in-place Cholesky (lower)
    for (int c = 0; c < DIM; c++) {
        float d = G[c][c];
        for (int k = 0; k < c; k++) d -= G[c][k] * G[c][k];
        d = sqrtf(fmaxf(d, 1e-30f));
        G[c][c] = d;
        float inv = 1.f / d;
        for (int r = c + 1; r < DIM; r++) {
            float s = G[r][c];
            for (int k = 0; k < c; k++) s -= G[r][k] * G[c][k];
            G[r][c] = s * inv;
        }
    }
    // L wv = gx
    float wv[DIM];
    for (int r = 0; r < DIM; r++) {
        float s = gx[r];
        for (int k = 0; k < r; k++) s -= G[r][k] * wv[k];
        wv[r] = s / G[r][r];
    }
    // L^T u = wv
    float u[DIM];
    for (int r = DIM - 1; r >= 0; r--) {
        float s = wv[r];
        for (int k = r + 1; k < DIM; k++) s -= G[k][r] * u[k];
        u[r] = s / G[r][r];
    }
    for (int j = 0; j < DIM; j++) out[b * DIM + j] = -u[j];
}

extern "C" void kernel_launch(void* const* d_in, const int* in_sizes, int n_in,
                              void* d_out, int out_size)
{
    Weights w;
    const float* x  = (const float*)d_in[0];
    const float* xs = (const float*)d_in[1];
    w.W0 = (const float*)d_in[2];  w.b0 = (const float*)d_in[3];
    w.W1 = (const float*)d_in[4];  w.b1 = (const float*)d_in[5];
    w.W2 = (const float*)d_in[6];  w.b2 = (const float*)d_in[7];
    w.W3 = (const float*)d_in[8];  w.b3 = (const float*)d_in[9];
    w.W4 = (const float*)d_in[10]; w.b4 = (const float*)d_in[11];
    float* out = (float*)d_out;

    const int xsCTAs = (NB + ROWS - 1) / ROWS;   // 61
    flow_kernel<<<NB + xsCTAs, NTHREADS>>>(x, xs, w);
    solve_kernel<<<(NB + 127) / 128, 128>>>(out);
}

// round 3
// speedup vs baseline: 1.2604x; 1.2604x over previous
#include <cuda_runtime.h>
#include <math.h>

#define DIM      16
#define HID      128
#define NB       1024
#define NSTEPS   10
#define ROWS     18          // row 0: primal x, rows 1..16: tangents, row 17: primal x_star
#define NTHREADS 128
#define W4T_LD   132         // padded leading dim for transposed W4 (bank-conflict mitigation)

// Intermediate storage (no allocations allowed)
__device__ float g_Y[2 * NB * DIM];        // y_comb: [2048][16]
__device__ float g_J[NB * DIM * DIM];      // J[b][i][j] = d flow(x)_i / d x_j

struct Weights {
    const float* W0; const float* b0;
    const float* W1; const float* b1;
    const float* W2; const float* b2;
    const float* W3; const float* b3;
    const float* W4; const float* b4;
};

struct Smem {
    float Z[ROWS][DIM];       // integration state
    float Zin[ROWS][DIM];     // vel input
    float Ks[ROWS][DIM];      // RK4 accumulator
    float V[ROWS][DIM];       // vel output
    float H[2][ROWS][HID];    // hidden ping-pong
    float W4T[DIM][W4T_LD];   // transposed final-layer weights (W4T[out][i] = W4[i][out])
};

// ---- packed fp32x2 helpers (sm_100+ packed FFMA: 2 lane-FMAs per instruction) ----
__device__ __forceinline__ void ffma2(unsigned long long& d,
                                      unsigned long long a,
                                      unsigned long long b) {
    asm("fma.rn.f32x2 %0, %1, %2, %0;" : "+l"(d) : "l"(a), "l"(b));
}
__device__ __forceinline__ unsigned long long pack2(float a, float b) {
    unsigned long long r;
    asm("mov.b64 %0, {%1, %2};" : "=l"(r) : "f"(a), "f"(b));
    return r;
}
__device__ __forceinline__ float red2(unsigned long long v) {
    float lo, hi;
    asm("mov.b64 {%0, %1}, %2;" : "=f"(lo), "=f"(hi) : "l"(v));
    return lo + hi;
}

// One velocity-field evaluation for all 18 state rows.
// Rows 0 and 17 are primals (bias + t column + tanh); rows 1..16 are tangents
// (no bias/t, scaled by (1 - h0^2) of the row-0 primal).
__device__ __forceinline__ void vel_eval(Smem& sm, float t, const Weights& w)
{
    const int j = threadIdx.x;
    unsigned long long acc[ROWS];

    // ---- layer 0: 16 (+t for primals) -> 128 ----
    {
        float bt = fmaf(t, __ldg(w.W0 + DIM * HID + j), __ldg(w.b0 + j));
        unsigned long long binit = pack2(bt, 0.f);
        #pragma unroll
        for (int s = 0; s < ROWS; s++) acc[s] = (s == 0 || s == ROWS - 1) ? binit : 0ull;

        #pragma unroll
        for (int i = 0; i < DIM; i += 4) {
            float w0 = __ldg(w.W0 + (i + 0) * HID + j);
            float w1 = __ldg(w.W0 + (i + 1) * HID + j);
            float w2 = __ldg(w.W0 + (i + 2) * HID + j);
            float w3 = __ldg(w.W0 + (i + 3) * HID + j);
            unsigned long long wa = pack2(w0, w1), wb = pack2(w2, w3);
            #pragma unroll
            for (int s = 0; s < ROWS; s++) {
                ulonglong2 hv = *reinterpret_cast<const ulonglong2*>(&sm.Zin[s][i]);
                ffma2(acc[s], hv.x, wa);
                ffma2(acc[s], hv.y, wb);
            }
        }
        float h0 = tanhf(red2(acc[0]));
        float g  = 1.f - h0 * h0;
        sm.H[0][0][j] = h0;
        #pragma unroll
        for (int s = 1; s < ROWS - 1; s++) sm.H[0][s][j] = g * red2(acc[s]);
        sm.H[0][ROWS - 1][j] = tanhf(red2(acc[ROWS - 1]));
    }
    __syncthreads();

    // ---- layers 1..3: 128 -> 128 ----
    #pragma unroll 1
    for (int L = 0; L < 3; L++) {
        const float* W  = (L == 0) ? w.W1 : (L == 1) ? w.W2 : w.W3;
        const float* bb = (L == 0) ? w.b1 : (L == 1) ? w.b2 : w.b3;
        const float (*Hin)[HID] = sm.H[L & 1];
        float (*Hout)[HID]      = sm.H[(L + 1) & 1];

        float bj = __ldg(bb + j);
        unsigned long long binit = pack2(bj, 0.f);
        #pragma unroll
        for (int s = 0; s < ROWS; s++) acc[s] = (s == 0 || s == ROWS - 1) ? binit : 0ull;

        #pragma unroll 2
        for (int i = 0; i < HID; i += 4) {
            float w0 = __ldg(W + (i + 0) * HID + j);
            float w1 = __ldg(W + (i + 1) * HID + j);
            float w2 = __ldg(W + (i + 2) * HID + j);
            float w3 = __ldg(W + (i + 3) * HID + j);
            unsigned long long wa = pack2(w0, w1), wb = pack2(w2, w3);
            #pragma unroll
            for (int s = 0; s < ROWS; s++) {
                ulonglong2 hv = *reinterpret_cast<const ulonglong2*>(&Hin[s][i]);
                ffma2(acc[s], hv.x, wa);
                ffma2(acc[s], hv.y, wb);
            }
        }
        float h0 = tanhf(red2(acc[0]));
        float g  = 1.f - h0 * h0;
        Hout[0][j] = h0;
        #pragma unroll
        for (int s = 1; s < ROWS - 1; s++) Hout[s][j] = g * red2(acc[s]);
        Hout[ROWS - 1][j] = tanhf(red2(acc[ROWS - 1]));
        __syncthreads();
    }

    // ---- layer 4: 128 -> 16 (linear). Final hidden lives in H[1]. ----
    // (out, row-group) decomposition: all 128 threads active.
    {
        const int out = j & 15, rg = j >> 4;
        #pragma unroll
        for (int p = 0; p < 3; p++) {
            int row = rg + p * 8;
            if (row < ROWS) {
                unsigned long long a = 0ull;
                #pragma unroll 4
                for (int i = 0; i < HID; i += 4) {
                    ulonglong2 hv = *reinterpret_cast<const ulonglong2*>(&sm.H[1][row][i]);
                    ulonglong2 wv = *reinterpret_cast<const ulonglong2*>(&sm.W4T[out][i]);
                    ffma2(a, hv.x, wv.x);
                    ffma2(a, hv.y, wv.y);
                }
                float r = red2(a);
                if (row == 0 || row == ROWS - 1) r += __ldg(w.b4 + out);
                sm.V[row][out] = r;
            }
        }
    }
    __syncthreads();
}

__global__ __launch_bounds__(NTHREADS, 7) void flow_kernel(
    const float* __restrict__ x, const float* __restrict__ xs, Weights w)
{
    __shared__ Smem sm;
    const int tid = threadIdx.x;
    const int b = blockIdx.x;

    // stage transposed W4 into shared (read once, reused 40x)
    for (int e = tid; e < DIM * HID; e += NTHREADS) {
        int out = e & 15, i = e >> 4;
        sm.W4T[out][i] = __ldg(w.W4 + e);   // W4 is [HID][DIM] row-major -> e = i*16+out
    }

    // init state rows
    for (int e = tid; e < ROWS * DIM; e += NTHREADS) {
        int r = e >> 4, c = e & 15;
        float v;
        if (r == 0)               v = x [b * DIM + c];
        else if (r == ROWS - 1)   v = xs[b * DIM + c];
        else                      v = ((r - 1) == c) ? 1.f : 0.f;
        sm.Z[r][c] = v; sm.Zin[r][c] = v;
    }
    __syncthreads();

    const float dt = 1.f / NSTEPS;
    #pragma unroll 1
    for (int st = 0; st < 4 * NSTEPS; st++) {
        const int ph = st & 3;
        float t = (st >> 2) * dt;
        if (ph == 1 || ph == 2) t += 0.5f * dt;
        else if (ph == 3)       t += dt;

        vel_eval(sm, t, w);

        for (int e = tid; e < ROWS * DIM; e += NTHREADS) {
            int r = e >> 4, c = e & 15;
            float v = sm.V[r][c];
            if (ph == 0) {
                sm.Ks[r][c]  = v;
                sm.Zin[r][c] = sm.Z[r][c] + 0.5f * dt * v;
            } else if (ph == 1) {
                sm.Ks[r][c] += 2.f * v;
                sm.Zin[r][c] = sm.Z[r][c] + 0.5f * dt * v;
            } else if (ph == 2) {
                sm.Ks[r][c] += 2.f * v;
                sm.Zin[r][c] = sm.Z[r][c] + dt * v;
            } else {
                float z = sm.Z[r][c] + (sm.Ks[r][c] + v) * (dt / 6.f);
                sm.Z[r][c]   = z;
                sm.Zin[r][c] = z;
            }
        }
        __syncthreads();
    }

    // writeback
    for (int e = tid; e < ROWS * DIM; e += NTHREADS) {
        int r = e >> 4, c = e & 15;
        if (r == 0)             g_Y[b * DIM + c]        = sm.Z[0][c];
        else if (r == ROWS - 1) g_Y[(NB + b) * DIM + c] = sm.Z[ROWS - 1][c];
        else                    g_J[b * DIM * DIM + c * DIM + (r - 1)] = sm.Z[r][c];
    }
}

// Per-sample: g = (y - y*)/(||y-y*||+1e-8); gx = J^T g; G = J^T J + 1e-6 I;
// out = -G^{-1} gx via Cholesky (G is SPD).
__global__ void solve_kernel(float* __restrict__ out)
{
    int b = blockIdx.x * blockDim.x + threadIdx.x;
    if (b >= NB) return;

    float Jm[DIM][DIM];
    for (int i = 0; i < DIM; i++)
        for (int j = 0; j < DIM; j++)
            Jm[i][j] = g_J[b * DIM * DIM + i * DIM + j];

    float diff[DIM]; float ss = 0.f;
    for (int i = 0; i < DIM; i++) {
        float d = g_Y[b * DIM + i] - g_Y[(NB + b) * DIM + i];
        diff[i] = d; ss += d * d;
    }
    float inorm = 1.f / (sqrtf(ss) + 1e-8f);

    float gx[DIM];
    for (int j = 0; j < DIM; j++) {
        float s = 0.f;
        for (int i = 0; i < DIM; i++) s += Jm[i][j] * diff[i];
        gx[j] = s * inorm;
    }

    float G[DIM][DIM];
    for (int j = 0; j < DIM; j++)
        for (int k = 0; k <= j; k++) {
            float s = 0.f;
            for (int i = 0; i < DIM; i++) s += Jm[i][j] * Jm[i][k];
            G[j][k] = s; G[k][j] = s;
        }
    for (int j = 0; j < DIM; j++) G[j][j] += 1e-6f;

    // in-place Cholesky (lower)
    for (int c = 0; c < DIM; c++) {
        float d = G[c][c];
        for (int k = 0; k < c; k++) d -= G[c][k] * G[c][k];
        d = sqrtf(fmaxf(d, 1e-30f));
        G[c][c] = d;
        float inv = 1.f / d;
        for (int r = c + 1; r < DIM; r++) {
            float s = G[r][c];
            for (int k = 0; k < c; k++) s -= G[r][k] * G[c][k];
            G[r][c] = s * inv;
        }
    }
    float wv[DIM];
    for (int r = 0; r < DIM; r++) {
        float s = gx[r];
        for (int k = 0; k < r; k++) s -= G[r][k] * wv[k];
        wv[r] = s / G[r][r];
    }
    float u[DIM];
    for (int r = DIM - 1; r >= 0; r--) {
        float s = wv[r];
        for (int k = r + 1; k < DIM; k++) s -= G[k][r] * u[k];
        u[r] = s / G[r][r];
    }
    for (int j = 0; j < DIM; j++) out[b * DIM + j] = -u[j];
}

extern "C" void kernel_launch(void* const* d_in, const int* in_sizes, int n_in,
                              void* d_out, int out_size)
{
    Weights w;
    const float* x  = (const float*)d_in[0];
    const float* xs = (const float*)d_in[1];
    w.W0 = (const float*)d_in[2];  w.b0 = (const float*)d_in[3];
    w.W1 = (const float*)d_in[4];  w.b1 = (const float*)d_in[5];
    w.W2 = (const float*)d_in[6];  w.b2 = (const float*)d_in[7];
    w.W3 = (const float*)d_in[8];  w.b3 = (const float*)d_in[9];
    w.W4 = (const float*)d_in[10]; w.b4 = (const float*)d_in[11];
    float* out = (float*)d_out;

    flow_kernel<<<NB, NTHREADS>>>(x, xs, w);
    solve_kernel<<<NB / 32, 32>>>(out);
}